// round 1
// baseline (speedup 1.0000x reference)
#include <cuda_runtime.h>
#include <math.h>
#include <float.h>

// MMCL loss, B=1024 rows of N=32768, P=8 positives, H=327 hard negatives.
// One CTA per row: stream row from HBM once, compact candidate negatives
// (> threshold) to smem, exact 327th-largest via histogram + rank, then
// closed-form loss per row. Second kernel reduces 1024 partials to scalar.

#define Bn   1024
#define Nn   32768
#define Pp   8
#define Kk   327
#define CAP  6144
#define NT   256

__device__ float g_partial[Bn];

__device__ __forceinline__ unsigned fkey(float f){
    unsigned u = __float_as_uint(f);
    return (u & 0x80000000u) ? ~u : (u | 0x80000000u);
}

__global__ __launch_bounds__(NT) void mmcl_row_kernel(
    const float* __restrict__ logits,
    const unsigned char* __restrict__ tg)
{
    const int r = blockIdx.x, tid = threadIdx.x;
    const int lane = tid & 31, wid = tid >> 5;

    __shared__ float s_cand[CAP];
    __shared__ int   s_hist[256];
    __shared__ float s_tbuf[256];
    __shared__ float s_pos[Pp];
    __shared__ float s_red[NT/32];
    __shared__ int s_cnt, s_pcnt, s_tc, s_bstar, s_above, s_gt;
    __shared__ unsigned s_maxkey;
    __shared__ float s_T, s_lob, s_hib, s_tau;

    if (tid == 0){ s_T = 1.5f; s_lob = -30.f; s_hib = 30.f; }

    const float4* __restrict__ L4 = (const float4*)(logits + (size_t)r * Nn);
    const uchar4* __restrict__ T4 = (const uchar4*)(tg + (size_t)r * Nn);

    float lmax = -FLT_MAX;
    int cnt = 0;

    // Streaming pass with (statistically never-taken) bisection retry so the
    // candidate filter is exact for any input.
    for (int attempt = 0; attempt < 64; ++attempt){
        __syncthreads();
        if (tid == 0){ s_cnt = 0; s_pcnt = 0; s_maxkey = 0u; }
        __syncthreads();
        const float Tl = s_T;
        for (int j = tid; j < Nn/4; j += NT){
            float4 v = L4[j]; uchar4 t = T4[j];
            float vv[4]; vv[0]=v.x; vv[1]=v.y; vv[2]=v.z; vv[3]=v.w;
            unsigned char tt[4]; tt[0]=t.x; tt[1]=t.y; tt[2]=t.z; tt[3]=t.w;
            #pragma unroll
            for (int e = 0; e < 4; ++e){
                float x = vv[e];
                lmax = fmaxf(lmax, x);
                bool isp = (tt[e] != 0);
                if (isp){
                    int ip = atomicAdd(&s_pcnt, 1);
                    if (ip < Pp) s_pos[ip] = x;
                }
                bool c = (!isp) && (x > Tl);
                unsigned m = __ballot_sync(0xffffffffu, c);
                if (c){
                    int rank   = __popc(m & ((1u << lane) - 1u));
                    int leader = __ffs(m) - 1;
                    int base;
                    if (lane == leader) base = atomicAdd(&s_cnt, __popc(m));
                    base = __shfl_sync(m, base, leader);
                    int pidx = base + rank;
                    if (pidx < CAP) s_cand[pidx] = x;
                }
            }
        }
        __syncthreads();
        cnt = s_cnt;
        if (cnt >= Kk && cnt <= CAP) break;
        if (tid == 0){
            if (cnt < Kk) s_hib = s_T; else s_lob = s_T;
            s_T = 0.5f * (s_lob + s_hib);
        }
    }
    const float Tl = s_T;
    if (cnt > CAP) cnt = CAP;   // unreachable in practice

    // Row max (for logsumexp stability)
    unsigned mk = fkey(lmax);
    #pragma unroll
    for (int o = 16; o; o >>= 1) mk = max(mk, __shfl_xor_sync(0xffffffffu, mk, o));
    if (lane == 0) atomicMax(&s_maxkey, mk);
    __syncthreads();
    unsigned gk = s_maxkey;
    float M = (gk & 0x80000000u) ? __uint_as_float(gk ^ 0x80000000u)
                                 : __uint_as_float(~gk);

    // Value-linear histogram over candidates to locate the Kk-th largest.
    for (int b = tid; b < 256; b += NT) s_hist[b] = 0;
    __syncthreads();
    const float scale = 256.0f / (M - Tl);
    for (int i = tid; i < cnt; i += NT){
        float v = s_cand[i];
        int b = (int)((v - Tl) * scale);
        b = min(max(b, 0), 255);
        atomicAdd(&s_hist[b], 1);
    }
    __syncthreads();
    if (tid == 0){
        int cum = 0, bs = 0;
        for (int b = 255; b >= 0; --b){
            int h = s_hist[b];
            if (cum + h >= Kk){ bs = b; break; }
            cum += h;
        }
        s_bstar = bs; s_above = cum; s_tc = 0;
    }
    __syncthreads();
    const int bstar = s_bstar, above = s_above;
    const int need  = Kk - above;

    // Exact tau (Kk-th largest) with tie count.
    if (s_hist[bstar] <= 256){
        for (int i = tid; i < cnt; i += NT){
            float v = s_cand[i];
            int b = (int)((v - Tl) * scale); b = min(max(b, 0), 255);
            if (b == bstar){ int p = atomicAdd(&s_tc, 1); s_tbuf[p] = v; }
        }
        __syncthreads();
        int tc = s_tc;
        if (tid < tc){
            float v = s_tbuf[tid]; int gt = 0, eq = 0;
            for (int k2 = 0; k2 < tc; ++k2){
                float w = s_tbuf[k2];
                gt += (w > v); eq += (w == v);
            }
            if (gt < need && need <= gt + eq){ s_tau = v; s_gt = above + gt; }
        }
    } else {
        // Degenerate fallback: exact O(n^2) rank over all candidates.
        for (int i = tid; i < cnt; i += NT){
            float v = s_cand[i]; int gt = 0, eq = 0;
            for (int k2 = 0; k2 < cnt; ++k2){
                float w = s_cand[k2];
                gt += (w > v); eq += (w == v);
            }
            if (gt < Kk && Kk <= gt + eq){ s_tau = v; s_gt = gt; }
        }
    }
    __syncthreads();
    const float tau = s_tau;
    const int   gtc = s_gt;

    // S = sum over top-Kk negatives of exp(10*(v - M)), ties at tau handled exactly.
    float acc = 0.f;
    for (int i = tid; i < cnt; i += NT){
        float v = s_cand[i];
        if (v > tau) acc += expf(10.f * (v - M));
    }
    #pragma unroll
    for (int o = 16; o; o >>= 1) acc += __shfl_xor_sync(0xffffffffu, acc, o);
    if (lane == 0) s_red[wid] = acc;
    __syncthreads();

    if (tid == 0){
        float S = (float)(Kk - gtc) * expf(10.f * (tau - M));
        #pragma unroll
        for (int w = 0; w < NT/32; ++w) S += s_red[w];

        float p[Pp];
        #pragma unroll
        for (int i = 0; i < Pp; ++i) p[i] = s_pos[i];
        // insertion sort descending
        for (int i = 1; i < Pp; ++i){
            float x = p[i]; int j = i - 1;
            while (j >= 0 && p[j] < x){ p[j+1] = p[j]; --j; }
            p[j+1] = x;
        }
        float e[Pp], suf[Pp+1]; suf[Pp] = 0.f;
        for (int i = Pp-1; i >= 0; --i){
            e[i] = expf(10.f * (p[i] - M));
            suf[i] = suf[i+1] + e[i];
        }
        float lsum = 0.f;
        for (int i = 0; i < Pp; ++i){
            float inner = (float)(Pp - i) * e[i] + suf[Pp - i] + S;
            lsum += logf(inner) + 10.f * (M - p[i]);
        }
        g_partial[r] = lsum;
    }
}

__global__ void mmcl_reduce_kernel(float* out, int out_size){
    __shared__ float sr[256];
    int tid = threadIdx.x;
    float a = 0.f;
    for (int i = tid; i < Bn; i += 256) a += g_partial[i];
    sr[tid] = a;
    __syncthreads();
    for (int s = 128; s > 0; s >>= 1){
        if (tid < s) sr[tid] += sr[tid + s];
        __syncthreads();
    }
    if (tid == 0){
        float val = sr[0] * (1.0f / (float)(Bn * Pp));
        for (int i = 0; i < out_size; ++i) out[i] = val;
    }
}

extern "C" void kernel_launch(void* const* d_in, const int* in_sizes, int n_in,
                              void* d_out, int out_size)
{
    const float* logits = (const float*)d_in[0];
    const unsigned char* targets = (const unsigned char*)d_in[1];
    mmcl_row_kernel<<<Bn, NT>>>(logits, targets);
    mmcl_reduce_kernel<<<1, 256>>>((float*)d_out, out_size);
}